// round 1
// baseline (speedup 1.0000x reference)
#include <cuda_runtime.h>
#include <cuda_fp16.h>
#include <cstdint>

#define D_VOCAB 262
#define D_EMB   128
#define NTAP    5
#define CW      16
#define NSEQ    32768
#define NCHUNK  148
#define THREADS 512
// smem: [NTAP*D_VOCAB] rows of 64 channels (32 x __half2) = 167,680 bytes
#define SMEM_BYTES (NTAP * D_VOCAB * 32 * 4)

// fp16 contrib table: [tap][vocab][emb]
__device__ __align__(16) __half g_tab[NTAP * D_VOCAB * D_EMB];
__device__ int g_stride2;  // 1 if ids are int64 (read every other 32-bit word)

// ---------------------------------------------------------------------------
// Detect int64 vs int32 ids: int64 ids (<262) have all-zero high words.
// ---------------------------------------------------------------------------
__global__ void detect_kernel(const int* __restrict__ p) {
    __shared__ int flag;
    if (threadIdx.x == 0) flag = 0;
    __syncthreads();
    int acc = 0;
    for (int i = threadIdx.x; i < 4096; i += blockDim.x)
        acc |= p[2 * i + 1];
    if (acc) atomicOr(&flag, 1);
    __syncthreads();
    if (threadIdx.x == 0) g_stride2 = (flag == 0) ? 1 : 0;
}

// ---------------------------------------------------------------------------
// Precompute contrib[k][v][e] = sum_i conv_w[e,i,k] * emb[v,i]   (fp32 -> fp16)
// Grid: ceil(262/5)=53 blocks of 128 threads (thread = output channel e).
// ---------------------------------------------------------------------------
__global__ void precompute_kernel(const float* __restrict__ emb,
                                  const float* __restrict__ conv_w) {
    __shared__ float se[5][D_EMB];
    const int vbase = blockIdx.x * 5;
    const int e = threadIdx.x;

    #pragma unroll
    for (int v = 0; v < 5; ++v) {
        int vv = vbase + v;
        se[v][e] = (vv < D_VOCAB) ? emb[vv * D_EMB + e] : 0.f;
    }
    __syncthreads();

    float acc[5][NTAP];
    #pragma unroll
    for (int v = 0; v < 5; ++v)
        #pragma unroll
        for (int k = 0; k < NTAP; ++k) acc[v][k] = 0.f;

    const float* wp = conv_w + (size_t)e * (D_EMB * NTAP);  // [i][k] for this e
    for (int i = 0; i < D_EMB; ++i) {
        float wk[NTAP];
        #pragma unroll
        for (int k = 0; k < NTAP; ++k) wk[k] = wp[i * NTAP + k];
        #pragma unroll
        for (int v = 0; v < 5; ++v) {
            float x = se[v][i];
            #pragma unroll
            for (int k = 0; k < NTAP; ++k) acc[v][k] = fmaf(wk[k], x, acc[v][k]);
        }
    }

    #pragma unroll
    for (int v = 0; v < 5; ++v) {
        int vv = vbase + v;
        if (vv < D_VOCAB) {
            #pragma unroll
            for (int k = 0; k < NTAP; ++k)
                g_tab[(k * D_VOCAB + vv) * D_EMB + e] = __float2half(acc[v][k]);
        }
    }
}

// ---------------------------------------------------------------------------
// Main kernel. Grid (148, 2): x = sequence chunk, y = 64-channel group.
// Each CTA stages its 5x262x64 fp16 slice in smem (164 KB), then each warp
// processes sequences: 74 conflict-free 128B LDS rows + hadd2/hmax2 per seq.
// ---------------------------------------------------------------------------
__global__ void __launch_bounds__(THREADS, 1)
conv_char_kernel(const int* __restrict__ ids_raw,
                 const float* __restrict__ conv_b,
                 float* __restrict__ out) {
    extern __shared__ __half2 s_tab[];  // [(k*262+v)*32 + lane]
    const int g = blockIdx.y;

    // Stage table slice: 10480 uint4 copies, coalesced.
    {
        const char* gb = (const char*)g_tab;
        uint4* dst = (uint4*)s_tab;
        for (int idx = threadIdx.x; idx < NTAP * D_VOCAB * 8; idx += THREADS) {
            int r = idx >> 3, q = idx & 7;
            dst[idx] = *(const uint4*)(gb + (size_t)r * 256 + g * 128 + q * 16);
        }
    }
    __syncthreads();

    const int lane = threadIdx.x & 31;
    const int warp = threadIdx.x >> 5;
    const int s2 = g_stride2;  // uniform

    const int chunk = (NSEQ + NCHUNK - 1) / NCHUNK;  // 222
    const int base = blockIdx.x * chunk;
    const int end = min(base + chunk, NSEQ);

    const float2 bias = *(const float2*)(conv_b + g * 64 + 2 * lane);

    for (int n = base + warp; n < end; n += (THREADS / 32)) {
        int idv[CW];
        if (s2) {  // int64 ids: 16 x 8B = 8 uint4 loads, ids in .x/.z
            const uint4* q4 = (const uint4*)(ids_raw + (size_t)n * 32);
            #pragma unroll
            for (int j = 0; j < 8; ++j) {
                uint4 q = q4[j];
                idv[2 * j]     = (int)q.x;
                idv[2 * j + 1] = (int)q.z;
            }
        } else {   // int32 ids: 16 x 4B = 4 int4 loads
            const int4* q4 = (const int4*)(ids_raw + (size_t)n * 16);
            #pragma unroll
            for (int j = 0; j < 4; ++j) {
                int4 q = q4[j];
                idv[4 * j] = q.x; idv[4 * j + 1] = q.y;
                idv[4 * j + 2] = q.z; idv[4 * j + 3] = q.w;
            }
        }

        __half2 m;
        #pragma unroll
        for (int t = 0; t < CW; ++t) {
            // center tap (k=2, c=t) always valid
            __half2 y = s_tab[(2 * D_VOCAB + idv[t]) * 32 + lane];
            #pragma unroll
            for (int k = 0; k < NTAP; ++k) {
                if (k == 2) continue;
                int c = t + k - 2;
                if (c < 0 || c >= CW) continue;  // folds at compile time
                y = __hadd2(y, s_tab[(k * D_VOCAB + idv[c]) * 32 + lane]);
            }
            m = (t == 0) ? y : __hmax2(m, y);
        }

        float2 r = __half22float2(m);
        r.x += bias.x; r.y += bias.y;
        *(float2*)(out + (size_t)n * D_EMB + g * 64 + 2 * lane) = r;
    }
}

// ---------------------------------------------------------------------------
extern "C" void kernel_launch(void* const* d_in, const int* in_sizes, int n_in,
                              void* d_out, int out_size) {
    // Select inputs by element count (robust to metadata ordering).
    const int* input = nullptr;
    const float* emb = nullptr;
    const float* conv_w = nullptr;
    const float* conv_b = nullptr;
    for (int i = 0; i < n_in; ++i) {
        switch (in_sizes[i]) {
            case 524288: input  = (const int*)d_in[i];   break;  // ids [128,256,16]
            case 33536:  emb    = (const float*)d_in[i]; break;  // [262,128]
            case 81920:  conv_w = (const float*)d_in[i]; break;  // [128,128,5]
            case 128:    conv_b = (const float*)d_in[i]; break;  // [128]
            default: break;  // lengths (32768) unused
        }
    }

    detect_kernel<<<1, 256>>>(input);
    precompute_kernel<<<(D_VOCAB + 4) / 5, 128>>>(emb, conv_w);

    cudaFuncSetAttribute(conv_char_kernel,
                         cudaFuncAttributeMaxDynamicSharedMemorySize, SMEM_BYTES);
    conv_char_kernel<<<dim3(NCHUNK, 2), THREADS, SMEM_BYTES>>>(
        input, conv_b, (float*)d_out);
}

// round 2
// speedup vs baseline: 1.0456x; 1.0456x over previous
#include <cuda_runtime.h>
#include <cuda_fp16.h>
#include <cstdint>

#define D_VOCAB 262
#define D_EMB   128
#define NTAP    5
#define CW      16
#define NSEQ    32768
#define NCHUNK  148
#define THREADS 512
// smem: [NTAP*D_VOCAB] rows of 64 channels (32 x __half2) = 167,680 bytes
#define SMEM_BYTES (NTAP * D_VOCAB * 32 * 4)
// half2-index stride of one tap plane: 262 rows * 32 half2
#define TAPSTRIDE (D_VOCAB * 32)

// fp16 contrib table: [tap][vocab][emb]
__device__ __align__(16) __half g_tab[NTAP * D_VOCAB * D_EMB];

// ---------------------------------------------------------------------------
// Precompute contrib[k][v][e] = sum_i conv_w[e,i,k] * emb[v,i]   (fp32 -> fp16)
// ---------------------------------------------------------------------------
__global__ void precompute_kernel(const float* __restrict__ emb,
                                  const float* __restrict__ conv_w) {
    __shared__ float se[5][D_EMB];
    const int vbase = blockIdx.x * 5;
    const int e = threadIdx.x;

    #pragma unroll
    for (int v = 0; v < 5; ++v) {
        int vv = vbase + v;
        se[v][e] = (vv < D_VOCAB) ? emb[vv * D_EMB + e] : 0.f;
    }
    __syncthreads();

    float acc[5][NTAP];
    #pragma unroll
    for (int v = 0; v < 5; ++v)
        #pragma unroll
        for (int k = 0; k < NTAP; ++k) acc[v][k] = 0.f;

    const float* wp = conv_w + (size_t)e * (D_EMB * NTAP);
    for (int i = 0; i < D_EMB; ++i) {
        float wk[NTAP];
        #pragma unroll
        for (int k = 0; k < NTAP; ++k) wk[k] = wp[i * NTAP + k];
        #pragma unroll
        for (int v = 0; v < 5; ++v) {
            float x = se[v][i];
            #pragma unroll
            for (int k = 0; k < NTAP; ++k) acc[v][k] = fmaf(wk[k], x, acc[v][k]);
        }
    }

    #pragma unroll
    for (int v = 0; v < 5; ++v) {
        int vv = vbase + v;
        if (vv < D_VOCAB) {
            #pragma unroll
            for (int k = 0; k < NTAP; ++k)
                g_tab[(k * D_VOCAB + vv) * D_EMB + e] = __float2half(acc[v][k]);
        }
    }
}

// ---------------------------------------------------------------------------
// Main kernel. Grid (148, 2): x = sequence chunk, y = 64-channel group.
// Each CTA stages its 5x262x64 fp16 slice in smem (164 KB).
// Each warp processes TWO sequences per iteration for 2x memory-level ILP.
// ---------------------------------------------------------------------------
__global__ void __launch_bounds__(THREADS, 1)
conv_char_kernel(const int* __restrict__ ids_raw,
                 const float* __restrict__ conv_b,
                 float* __restrict__ out) {
    extern __shared__ __half2 s_tab[];  // [(k*262+v)*32 + lane]
    __shared__ int s_s2;
    const int g = blockIdx.y;
    const int lane = threadIdx.x & 31;
    const int warp = threadIdx.x >> 5;

    // Inline int64-vs-int32 detection: int64 ids (<262) have zero high words.
    if (threadIdx.x < 32) {
        int v = ids_raw[2 * lane + 1] | ids_raw[64 + 2 * lane + 1];
        unsigned b = __ballot_sync(0xffffffffu, v != 0);
        if (lane == 0) s_s2 = (b == 0u) ? 1 : 0;
    }

    // Stage table slice: 10480 uint4 copies, coalesced.
    {
        const char* gb = (const char*)g_tab;
        uint4* dst = (uint4*)s_tab;
        for (int idx = threadIdx.x; idx < NTAP * D_VOCAB * 8; idx += THREADS) {
            int r = idx >> 3, q = idx & 7;
            dst[idx] = *(const uint4*)(gb + (size_t)r * 256 + g * 128 + q * 16);
        }
    }
    __syncthreads();

    const int s2 = s_s2;  // uniform across CTA

    const int chunk = (NSEQ + NCHUNK - 1) / NCHUNK;  // 222 (always even here)
    const int base = blockIdx.x * chunk;
    const int end = min(base + chunk, NSEQ);

    const float2 bias = *(const float2*)(conv_b + g * 64 + 2 * lane);
    const __half2* tab = s_tab + lane;

    // Two sequences per warp-iteration.
    for (int n0 = base + 2 * warp; n0 < end; n0 += 2 * (THREADS / 32)) {
        const int n1 = n0 + 1;  // chunk is even -> always valid

        // a[c] = id*32 (half2 row index); addresses add lane via `tab`.
        int aA[CW], aB[CW];
        if (s2) {  // int64 ids: 2 seqs = 32 x 8B = 16 uint4 loads
            const uint4* q4 = (const uint4*)(ids_raw + (size_t)n0 * 32);
            #pragma unroll
            for (int j = 0; j < 8; ++j) {
                uint4 q = q4[j];
                aA[2 * j]     = (int)q.x * 32;
                aA[2 * j + 1] = (int)q.z * 32;
            }
            #pragma unroll
            for (int j = 0; j < 8; ++j) {
                uint4 q = q4[8 + j];
                aB[2 * j]     = (int)q.x * 32;
                aB[2 * j + 1] = (int)q.z * 32;
            }
        } else {   // int32 ids
            const int4* q4 = (const int4*)(ids_raw + (size_t)n0 * 16);
            #pragma unroll
            for (int j = 0; j < 4; ++j) {
                int4 q = q4[j];
                aA[4 * j] = q.x * 32; aA[4 * j + 1] = q.y * 32;
                aA[4 * j + 2] = q.z * 32; aA[4 * j + 3] = q.w * 32;
            }
            #pragma unroll
            for (int j = 0; j < 4; ++j) {
                int4 q = q4[4 + j];
                aB[4 * j] = q.x * 32; aB[4 * j + 1] = q.y * 32;
                aB[4 * j + 2] = q.z * 32; aB[4 * j + 3] = q.w * 32;
            }
        }

        // Even/odd-t parallel max chains per sequence (shorter critical path).
        __half2 mA0, mA1, mB0, mB1;
        #pragma unroll
        for (int t = 0; t < CW; ++t) {
            // Valid taps: k in [0,5), c = t+k-2 in [0,16)
            const int klo = (t < 2) ? (2 - t) : 0;
            const int khi = (t > CW - 3) ? (CW + 1 - t) : NTAP - 1;  // inclusive

            __half2 yA, yB;
            {
                // gather terms, pairwise sum
                __half2 sA[NTAP], sB[NTAP];
                #pragma unroll
                for (int k = 0; k < NTAP; ++k) {
                    if (k < klo || k > khi) continue;
                    const int c = t + k - 2;
                    sA[k] = tab[k * TAPSTRIDE + aA[c]];
                    sB[k] = tab[k * TAPSTRIDE + aB[c]];
                }
                // pairwise-reduce the valid window [klo, khi]
                const int nv = khi - klo + 1;
                if (nv == 5) {
                    __half2 p0A = __hadd2(sA[0], sA[1]);
                    __half2 p1A = __hadd2(sA[2], sA[3]);
                    yA = __hadd2(__hadd2(p0A, p1A), sA[4]);
                    __half2 p0B = __hadd2(sB[0], sB[1]);
                    __half2 p1B = __hadd2(sB[2], sB[3]);
                    yB = __hadd2(__hadd2(p0B, p1B), sB[4]);
                } else if (nv == 4) {
                    __half2 p0A = __hadd2(sA[klo], sA[klo + 1]);
                    __half2 p1A = __hadd2(sA[klo + 2], sA[klo + 3]);
                    yA = __hadd2(p0A, p1A);
                    __half2 p0B = __hadd2(sB[klo], sB[klo + 1]);
                    __half2 p1B = __hadd2(sB[klo + 2], sB[klo + 3]);
                    yB = __hadd2(p0B, p1B);
                } else {  // nv == 3
                    yA = __hadd2(__hadd2(sA[klo], sA[klo + 1]), sA[klo + 2]);
                    yB = __hadd2(__hadd2(sB[klo], sB[klo + 1]), sB[klo + 2]);
                }
            }

            if (t == 0)      { mA0 = yA; mB0 = yB; }
            else if (t == 1) { mA1 = yA; mB1 = yB; }
            else if ((t & 1) == 0) { mA0 = __hmax2(mA0, yA); mB0 = __hmax2(mB0, yB); }
            else                   { mA1 = __hmax2(mA1, yA); mB1 = __hmax2(mB1, yB); }
        }
        __half2 mA = __hmax2(mA0, mA1);
        __half2 mB = __hmax2(mB0, mB1);

        float2 rA = __half22float2(mA);
        rA.x += bias.x; rA.y += bias.y;
        *(float2*)(out + (size_t)n0 * D_EMB + g * 64 + 2 * lane) = rA;

        float2 rB = __half22float2(mB);
        rB.x += bias.x; rB.y += bias.y;
        *(float2*)(out + (size_t)n1 * D_EMB + g * 64 + 2 * lane) = rB;
    }
}

// ---------------------------------------------------------------------------
extern "C" void kernel_launch(void* const* d_in, const int* in_sizes, int n_in,
                              void* d_out, int out_size) {
    const int* input = nullptr;
    const float* emb = nullptr;
    const float* conv_w = nullptr;
    const float* conv_b = nullptr;
    for (int i = 0; i < n_in; ++i) {
        switch (in_sizes[i]) {
            case 524288: input  = (const int*)d_in[i];   break;  // ids [128,256,16]
            case 33536:  emb    = (const float*)d_in[i]; break;  // [262,128]
            case 81920:  conv_w = (const float*)d_in[i]; break;  // [128,128,5]
            case 128:    conv_b = (const float*)d_in[i]; break;  // [128]
            default: break;  // lengths (32768) unused
        }
    }

    precompute_kernel<<<(D_VOCAB + 4) / 5, 128>>>(emb, conv_w);

    cudaFuncSetAttribute(conv_char_kernel,
                         cudaFuncAttributeMaxDynamicSharedMemorySize, SMEM_BYTES);
    conv_char_kernel<<<dim3(NCHUNK, 2), THREADS, SMEM_BYTES>>>(
        input, conv_b, (float*)d_out);
}

// round 3
// speedup vs baseline: 1.7086x; 1.6341x over previous
#include <cuda_runtime.h>
#include <cuda_fp16.h>
#include <cstdint>

#define D_VOCAB 262
#define D_EMB   128
#define NTAP    5
#define CW      16
#define NSEQ    32768
#define NCHUNK  148
#define THREADS 512
// smem: [NTAP*D_VOCAB] rows of 64 channels (16 x 8B) = 167,680 bytes
#define SMEM_BYTES (NTAP * D_VOCAB * 32 * 4)
// 8-byte-unit stride of one tap plane: 262 rows * 16 u64
#define TAPSTRIDE8 (D_VOCAB * 16)

// fp16 contrib table: [tap][vocab][emb]
__device__ __align__(16) __half g_tab[NTAP * D_VOCAB * D_EMB];
// transposed conv weights: [tap][i][e] fp32
__device__ __align__(16) float g_wt[NTAP * D_EMB * D_EMB];

// ---------------------------------------------------------------------------
// Transpose conv_w[e][i][k] -> g_wt[k][i][e].  Coalesced writes.
// ---------------------------------------------------------------------------
__global__ void transpose_w_kernel(const float* __restrict__ conv_w) {
    int idx = blockIdx.x * 256 + threadIdx.x;      // out index over [5][128][128]
    if (idx >= NTAP * D_EMB * D_EMB) return;
    int e = idx & 127;
    int i = (idx >> 7) & 127;
    int k = idx >> 14;
    g_wt[idx] = conv_w[e * (D_EMB * NTAP) + i * NTAP + k];
}

// ---------------------------------------------------------------------------
// Precompute contrib[k][v][e] = sum_i conv_w[e,i,k] * emb[v,i]   (fp32->fp16)
// Grid (33, 5): x = group of 8 vocab ids, y = tap.  128 threads = e.
// Coalesced g_wt loads; emb read as uniform-address float4 (L1 broadcast).
// ---------------------------------------------------------------------------
__global__ void precompute_kernel(const float* __restrict__ emb) {
    const int e = threadIdx.x;
    const int k = blockIdx.y;
    const int v0 = blockIdx.x * 8;
    const float* __restrict__ wt = g_wt + k * (D_EMB * D_EMB);  // [i][e]
    const float4* __restrict__ emb4 = (const float4*)emb;

    float acc[8];
    #pragma unroll
    for (int v = 0; v < 8; ++v) acc[v] = 0.f;

    #pragma unroll 2
    for (int i4 = 0; i4 < 32; ++i4) {
        float w0 = wt[(i4 * 4 + 0) * D_EMB + e];
        float w1 = wt[(i4 * 4 + 1) * D_EMB + e];
        float w2 = wt[(i4 * 4 + 2) * D_EMB + e];
        float w3 = wt[(i4 * 4 + 3) * D_EMB + e];
        #pragma unroll
        for (int v = 0; v < 8; ++v) {
            int vv = v0 + v;
            if (vv < D_VOCAB) {
                float4 em = __ldg(&emb4[vv * 32 + i4]);
                acc[v] = fmaf(em.x, w0, acc[v]);
                acc[v] = fmaf(em.y, w1, acc[v]);
                acc[v] = fmaf(em.z, w2, acc[v]);
                acc[v] = fmaf(em.w, w3, acc[v]);
            }
        }
    }

    #pragma unroll
    for (int v = 0; v < 8; ++v) {
        int vv = v0 + v;
        if (vv < D_VOCAB)
            g_tab[(k * D_VOCAB + vv) * D_EMB + e] = __float2half(acc[v]);
    }
}

// ---------------------------------------------------------------------------
// Main kernel. Grid (148, 2): x = sequence chunk, y = 64-channel group.
// CTA stages its 5x262x64 fp16 table slice (164 KB smem).
// Half-warp split: lanes 0-15 -> seq n0, lanes 16-31 -> seq n0+1.
// Each lane owns 4 channels (8 bytes) -> gathers are LDS.64, 2 wavefronts,
// conflict-free. 74 LDS per warp-iteration instead of 148.
// ---------------------------------------------------------------------------
__global__ void __launch_bounds__(THREADS, 1)
conv_char_kernel(const int* __restrict__ ids_raw,
                 const float* __restrict__ conv_b,
                 float* __restrict__ out) {
    extern __shared__ __half2 s_tab[];
    __shared__ int s_s2;
    const int g = blockIdx.y;
    const int lane = threadIdx.x & 31;
    const int warp = threadIdx.x >> 5;
    const int l15 = lane & 15;
    const int hi = (lane >> 4);          // 0 = seq A, 1 = seq B

    // Inline int64-vs-int32 detection (int64 ids < 262 -> zero high words).
    if (threadIdx.x < 32) {
        int v = ids_raw[2 * lane + 1] | ids_raw[64 + 2 * lane + 1];
        unsigned b = __ballot_sync(0xffffffffu, v != 0);
        if (lane == 0) s_s2 = (b == 0u) ? 1 : 0;
    }

    // Stage table slice: coalesced uint4 copies.
    {
        const char* gb = (const char*)g_tab;
        uint4* dst = (uint4*)s_tab;
        for (int idx = threadIdx.x; idx < NTAP * D_VOCAB * 8; idx += THREADS) {
            int r = idx >> 3, q = idx & 7;
            dst[idx] = *(const uint4*)(gb + (size_t)r * 256 + g * 128 + q * 16);
        }
    }
    __syncthreads();

    const int s2 = s_s2;
    const uint2* __restrict__ tab8 = (const uint2*)s_tab;  // 8B units

    const int chunk = (NSEQ + NCHUNK - 1) / NCHUNK;  // 222 (even)
    const int base = blockIdx.x * chunk;
    const int end = min(base + chunk, NSEQ);

    const float4 bias = *(const float4*)(conv_b + g * 64 + 4 * l15);

    for (int n0 = base + 2 * warp; n0 < end; n0 += 2 * (THREADS / 32)) {
        const int nsel = n0 + hi;   // this half-warp's sequence

        // a[c] = id*16 + l15  (uint2 index of this lane's 8B within the row)
        int a[CW];
        if (s2) {  // int64 ids: 16 ids x 8B = 8 uint4 per lane
            const uint4* q4 = (const uint4*)(ids_raw + (size_t)nsel * 32);
            #pragma unroll
            for (int j = 0; j < 8; ++j) {
                uint4 q = q4[j];
                a[2 * j]     = (int)q.x * 16 + l15;
                a[2 * j + 1] = (int)q.z * 16 + l15;
            }
        } else {   // int32 ids: 4 int4 per lane
            const int4* q4 = (const int4*)(ids_raw + (size_t)nsel * 16);
            #pragma unroll
            for (int j = 0; j < 4; ++j) {
                int4 q = q4[j];
                a[4 * j]     = q.x * 16 + l15;
                a[4 * j + 1] = q.y * 16 + l15;
                a[4 * j + 2] = q.z * 16 + l15;
                a[4 * j + 3] = q.w * 16 + l15;
            }
        }

        // Even/odd-t max chains, 2 half2 accumulators per lane (4 channels).
        __half2 me0, me1, mo0, mo1;
        #pragma unroll
        for (int t = 0; t < CW; ++t) {
            const int klo = (t < 2) ? (2 - t) : 0;
            const int khi = (t > CW - 3) ? (CW + 1 - t) : NTAP - 1;  // inclusive

            uint2 s[NTAP];
            #pragma unroll
            for (int k = 0; k < NTAP; ++k) {
                if (k < klo || k > khi) continue;
                s[k] = tab8[k * TAPSTRIDE8 + a[t + k - 2]];
            }

            __half2 y0, y1;
            const int nv = khi - klo + 1;
            if (nv == 5) {
                __half2 p0 = __hadd2(*(__half2*)&s[0].x, *(__half2*)&s[1].x);
                __half2 p1 = __hadd2(*(__half2*)&s[2].x, *(__half2*)&s[3].x);
                y0 = __hadd2(__hadd2(p0, p1), *(__half2*)&s[4].x);
                __half2 q0 = __hadd2(*(__half2*)&s[0].y, *(__half2*)&s[1].y);
                __half2 q1 = __hadd2(*(__half2*)&s[2].y, *(__half2*)&s[3].y);
                y1 = __hadd2(__hadd2(q0, q1), *(__half2*)&s[4].y);
            } else if (nv == 4) {
                __half2 p0 = __hadd2(*(__half2*)&s[klo].x, *(__half2*)&s[klo + 1].x);
                __half2 p1 = __hadd2(*(__half2*)&s[klo + 2].x, *(__half2*)&s[klo + 3].x);
                y0 = __hadd2(p0, p1);
                __half2 q0 = __hadd2(*(__half2*)&s[klo].y, *(__half2*)&s[klo + 1].y);
                __half2 q1 = __hadd2(*(__half2*)&s[klo + 2].y, *(__half2*)&s[klo + 3].y);
                y1 = __hadd2(q0, q1);
            } else {  // nv == 3
                y0 = __hadd2(__hadd2(*(__half2*)&s[klo].x, *(__half2*)&s[klo + 1].x),
                             *(__half2*)&s[klo + 2].x);
                y1 = __hadd2(__hadd2(*(__half2*)&s[klo].y, *(__half2*)&s[klo + 1].y),
                             *(__half2*)&s[klo + 2].y);
            }

            if (t == 0)      { me0 = y0; me1 = y1; }
            else if (t == 1) { mo0 = y0; mo1 = y1; }
            else if ((t & 1) == 0) { me0 = __hmax2(me0, y0); me1 = __hmax2(me1, y1); }
            else                   { mo0 = __hmax2(mo0, y0); mo1 = __hmax2(mo1, y1); }
        }
        __half2 m0 = __hmax2(me0, mo0);
        __half2 m1 = __hmax2(me1, mo1);

        float2 r0 = __half22float2(m0);
        float2 r1 = __half22float2(m1);
        float4 o;
        o.x = r0.x + bias.x; o.y = r0.y + bias.y;
        o.z = r1.x + bias.z; o.w = r1.y + bias.w;
        *(float4*)(out + (size_t)nsel * D_EMB + g * 64 + 4 * l15) = o;
    }
}

// ---------------------------------------------------------------------------
extern "C" void kernel_launch(void* const* d_in, const int* in_sizes, int n_in,
                              void* d_out, int out_size) {
    const int* input = nullptr;
    const float* emb = nullptr;
    const float* conv_w = nullptr;
    const float* conv_b = nullptr;
    for (int i = 0; i < n_in; ++i) {
        switch (in_sizes[i]) {
            case 524288: input  = (const int*)d_in[i];   break;  // ids [128,256,16]
            case 33536:  emb    = (const float*)d_in[i]; break;  // [262,128]
            case 81920:  conv_w = (const float*)d_in[i]; break;  // [128,128,5]
            case 128:    conv_b = (const float*)d_in[i]; break;  // [128]
            default: break;  // lengths (32768) unused
        }
    }

    transpose_w_kernel<<<(NTAP * D_EMB * D_EMB + 255) / 256, 256>>>(conv_w);
    precompute_kernel<<<dim3(33, NTAP), 128>>>(emb);

    cudaFuncSetAttribute(conv_char_kernel,
                         cudaFuncAttributeMaxDynamicSharedMemorySize, SMEM_BYTES);
    conv_char_kernel<<<dim3(NCHUNK, 2), THREADS, SMEM_BYTES>>>(
        input, conv_b, (float*)d_out);
}

// round 4
// speedup vs baseline: 1.8036x; 1.0556x over previous
#include <cuda_runtime.h>
#include <cuda_fp16.h>
#include <cstdint>

#define D_VOCAB 262
#define D_EMB   128
#define NTAP    5
#define CW      16
#define NSEQ    32768
#define NCHUNK  74
#define THREADS 512
// smem: [NTAP*D_VOCAB] rows of 64 channels (8 x uint4) = 167,680 bytes
#define SMEM_BYTES (NTAP * D_VOCAB * 32 * 4)
// uint4-unit stride of one tap plane: 262 rows * 8 uint4
#define TAPSTRIDE16 (D_VOCAB * 8)

// fp16 contrib table: [tap][vocab][emb]
__device__ __align__(16) __half g_tab[NTAP * D_VOCAB * D_EMB];
// transposed conv weights: g_t[(i*5+k)*128 + e] = conv_w[e][i][k]
__device__ __align__(16) float g_t[NTAP * D_EMB * D_EMB];

// ---------------------------------------------------------------------------
// Tiled transpose: conv_w [128 e][640 ik] -> g_t [640 ik][128 e].
// Coalesced on both sides via 32x33 smem tile.
// ---------------------------------------------------------------------------
__global__ void transpose_w_kernel(const float* __restrict__ conv_w) {
    __shared__ float tile[32][33];
    const int ik0 = blockIdx.x * 32;   // 20 blocks over 640
    const int e0 = blockIdx.y * 32;    // 4 blocks over 128
    const int tx = threadIdx.x;        // 0..31
    const int ty = threadIdx.y;        // 0..7

    #pragma unroll
    for (int r = ty; r < 32; r += 8)
        tile[r][tx] = conv_w[(e0 + r) * (D_EMB * NTAP) + ik0 + tx];
    __syncthreads();
    #pragma unroll
    for (int r = ty; r < 32; r += 8)
        g_t[(ik0 + r) * D_EMB + e0 + tx] = tile[tx][r];
}

// ---------------------------------------------------------------------------
// Precompute contrib[k][v][e] = sum_i conv_w[e,i,k] * emb[v,i]   (fp32->fp16)
// Grid (33, 5): x = group of 8 vocab ids, y = tap. 128 threads = e.
// g_t loads coalesced; emb read as uniform-address float4 (broadcast).
// ---------------------------------------------------------------------------
__global__ void precompute_kernel(const float* __restrict__ emb) {
    const int e = threadIdx.x;
    const int k = blockIdx.y;
    const int v0 = blockIdx.x * 8;
    const float4* __restrict__ emb4 = (const float4*)emb;

    float acc[8];
    #pragma unroll
    for (int v = 0; v < 8; ++v) acc[v] = 0.f;

    #pragma unroll 2
    for (int i4 = 0; i4 < 32; ++i4) {
        const int i = i4 * 4;
        float w0 = g_t[((i + 0) * NTAP + k) * D_EMB + e];
        float w1 = g_t[((i + 1) * NTAP + k) * D_EMB + e];
        float w2 = g_t[((i + 2) * NTAP + k) * D_EMB + e];
        float w3 = g_t[((i + 3) * NTAP + k) * D_EMB + e];
        #pragma unroll
        for (int v = 0; v < 8; ++v) {
            int vv = v0 + v;
            if (vv < D_VOCAB) {
                float4 em = __ldg(&emb4[vv * 32 + i4]);
                acc[v] = fmaf(em.x, w0, acc[v]);
                acc[v] = fmaf(em.y, w1, acc[v]);
                acc[v] = fmaf(em.z, w2, acc[v]);
                acc[v] = fmaf(em.w, w3, acc[v]);
            }
        }
    }

    #pragma unroll
    for (int v = 0; v < 8; ++v) {
        int vv = v0 + v;
        if (vv < D_VOCAB)
            g_tab[(k * D_VOCAB + vv) * D_EMB + e] = __float2half(acc[v]);
    }
}

// ---------------------------------------------------------------------------
// half2 x4 helpers on uint4-packed fp16
// ---------------------------------------------------------------------------
__device__ __forceinline__ uint4 h2add4(uint4 a, uint4 b) {
    uint4 r;
    *(__half2*)&r.x = __hadd2(*(const __half2*)&a.x, *(const __half2*)&b.x);
    *(__half2*)&r.y = __hadd2(*(const __half2*)&a.y, *(const __half2*)&b.y);
    *(__half2*)&r.z = __hadd2(*(const __half2*)&a.z, *(const __half2*)&b.z);
    *(__half2*)&r.w = __hadd2(*(const __half2*)&a.w, *(const __half2*)&b.w);
    return r;
}
__device__ __forceinline__ uint4 h2max4(uint4 a, uint4 b) {
    uint4 r;
    *(__half2*)&r.x = __hmax2(*(const __half2*)&a.x, *(const __half2*)&b.x);
    *(__half2*)&r.y = __hmax2(*(const __half2*)&a.y, *(const __half2*)&b.y);
    *(__half2*)&r.z = __hmax2(*(const __half2*)&a.z, *(const __half2*)&b.z);
    *(__half2*)&r.w = __hmax2(*(const __half2*)&a.w, *(const __half2*)&b.w);
    return r;
}

// ---------------------------------------------------------------------------
// Main kernel. Grid (74, 2): x = sequence chunk (443 seqs), y = 64-ch group.
// CTA stages its 5x262x64 fp16 table slice (164 KB smem), 1 CTA/SM, 1 wave.
// Quarter-warp split: lane group q = lane>>3 -> sequence n0+q; each lane owns
// 8 channels (16 B) so gathers are LDS.128 over 4 aligned 128-B rows:
// 4 wavefronts, conflict-free, 4 independent chains per warp.
// ---------------------------------------------------------------------------
__global__ void __launch_bounds__(THREADS, 1)
conv_char_kernel(const int* __restrict__ ids_raw,
                 const float* __restrict__ conv_b,
                 float* __restrict__ out) {
    extern __shared__ uint4 s_tab16[];
    __shared__ int s_s2;
    const int g = blockIdx.y;
    const int lane = threadIdx.x & 31;
    const int warp = threadIdx.x >> 5;
    const int l7 = lane & 7;
    const int q = lane >> 3;             // 0..3: which sequence of the group

    // Inline int64-vs-int32 detection (int64 ids < 262 -> zero high words).
    if (threadIdx.x < 32) {
        int v = ids_raw[2 * lane + 1] | ids_raw[64 + 2 * lane + 1];
        unsigned b = __ballot_sync(0xffffffffu, v != 0);
        if (lane == 0) s_s2 = (b == 0u) ? 1 : 0;
    }

    // Stage table slice: coalesced uint4 copies (10480 x 16 B).
    {
        const char* gb = (const char*)g_tab;
        for (int idx = threadIdx.x; idx < NTAP * D_VOCAB * 8; idx += THREADS) {
            int r = idx >> 3, c = idx & 7;
            s_tab16[idx] = *(const uint4*)(gb + (size_t)r * 256 + g * 128 + c * 16);
        }
    }
    __syncthreads();

    const int s2 = s_s2;

    const int chunk = (NSEQ + NCHUNK - 1) / NCHUNK;  // 443
    const int base = blockIdx.x * chunk;
    const int end = min(base + chunk, NSEQ);

    const float4 bias0 = *(const float4*)(conv_b + g * 64 + l7 * 8);
    const float4 bias1 = *(const float4*)(conv_b + g * 64 + l7 * 8 + 4);

    for (int n0 = base + 4 * warp; n0 < end; n0 += 4 * (THREADS / 32)) {
        const int nsel = n0 + q;
        const int nc = min(nsel, end - 1);   // clamp: duplicate work, store guarded

        // a[c] = id*8 + l7 (uint4 index of this lane's 16 B within the row)
        int a[CW];
        if (s2) {  // int64 ids: 8 x uint4 per lane
            const uint4* q4 = (const uint4*)(ids_raw + (size_t)nc * 32);
            #pragma unroll
            for (int j = 0; j < 8; ++j) {
                uint4 w = q4[j];
                a[2 * j]     = (int)w.x * 8 + l7;
                a[2 * j + 1] = (int)w.z * 8 + l7;
            }
        } else {   // int32 ids: 4 x int4 per lane
            const int4* q4 = (const int4*)(ids_raw + (size_t)nc * 16);
            #pragma unroll
            for (int j = 0; j < 4; ++j) {
                int4 w = q4[j];
                a[4 * j]     = w.x * 8 + l7;
                a[4 * j + 1] = w.y * 8 + l7;
                a[4 * j + 2] = w.z * 8 + l7;
                a[4 * j + 3] = w.w * 8 + l7;
            }
        }

        // Even/odd-t max chains on 8 channels (4 half2) per lane.
        uint4 me, mo;
        #pragma unroll
        for (int t = 0; t < CW; ++t) {
            const int klo = (t < 2) ? (2 - t) : 0;
            const int khi = (t > CW - 3) ? (CW + 1 - t) : NTAP - 1;  // inclusive

            uint4 s[NTAP];
            #pragma unroll
            for (int k = 0; k < NTAP; ++k) {
                if (k < klo || k > khi) continue;
                s[k] = s_tab16[k * TAPSTRIDE16 + a[t + k - 2]];
            }

            uint4 y;
            const int nv = khi - klo + 1;
            if (nv == 5) {
                y = h2add4(h2add4(h2add4(s[0], s[1]), h2add4(s[2], s[3])), s[4]);
            } else if (nv == 4) {
                y = h2add4(h2add4(s[klo], s[klo + 1]), h2add4(s[klo + 2], s[klo + 3]));
            } else {  // nv == 3
                y = h2add4(h2add4(s[klo], s[klo + 1]), s[klo + 2]);
            }

            if (t == 0)      me = y;
            else if (t == 1) mo = y;
            else if ((t & 1) == 0) me = h2max4(me, y);
            else                   mo = h2max4(mo, y);
        }
        const uint4 m = h2max4(me, mo);

        if (nsel < end) {
            float2 c0 = __half22float2(*(const __half2*)&m.x);
            float2 c1 = __half22float2(*(const __half2*)&m.y);
            float2 c2 = __half22float2(*(const __half2*)&m.z);
            float2 c3 = __half22float2(*(const __half2*)&m.w);
            float4 o0, o1;
            o0.x = c0.x + bias0.x; o0.y = c0.y + bias0.y;
            o0.z = c1.x + bias0.z; o0.w = c1.y + bias0.w;
            o1.x = c2.x + bias1.x; o1.y = c2.y + bias1.y;
            o1.z = c3.x + bias1.z; o1.w = c3.y + bias1.w;
            float* op = out + (size_t)nsel * D_EMB + g * 64 + l7 * 8;
            *(float4*)op = o0;
            *(float4*)(op + 4) = o1;
        }
    }
}

// ---------------------------------------------------------------------------
extern "C" void kernel_launch(void* const* d_in, const int* in_sizes, int n_in,
                              void* d_out, int out_size) {
    const int* input = nullptr;
    const float* emb = nullptr;
    const float* conv_w = nullptr;
    const float* conv_b = nullptr;
    for (int i = 0; i < n_in; ++i) {
        switch (in_sizes[i]) {
            case 524288: input  = (const int*)d_in[i];   break;  // ids [128,256,16]
            case 33536:  emb    = (const float*)d_in[i]; break;  // [262,128]
            case 81920:  conv_w = (const float*)d_in[i]; break;  // [128,128,5]
            case 128:    conv_b = (const float*)d_in[i]; break;  // [128]
            default: break;  // lengths (32768) unused
        }
    }

    transpose_w_kernel<<<dim3(20, 4), dim3(32, 8)>>>(conv_w);
    precompute_kernel<<<dim3(33, NTAP), 128>>>(emb);

    cudaFuncSetAttribute(conv_char_kernel,
                         cudaFuncAttributeMaxDynamicSharedMemorySize, SMEM_BYTES);
    conv_char_kernel<<<dim3(NCHUNK, 2), THREADS, SMEM_BYTES>>>(
        input, conv_b, (float*)d_out);
}

// round 5
// speedup vs baseline: 2.2038x; 1.2219x over previous
#include <cuda_runtime.h>
#include <cuda_fp16.h>
#include <cstdint>

#define D_VOCAB 262
#define D_EMB   128
#define NTAP    5
#define CW      16
#define NSEQ    32768
#define NCHUNK  74
#define THREADS 512
// main smem: [NTAP*D_VOCAB] rows of 64 channels (8 x uint4) = 167,680 bytes
#define SMEM_BYTES (NTAP * D_VOCAB * 32 * 4)
// uint4-unit stride of one tap plane: 262 rows * 8 uint4
#define TAPSTRIDE16 (D_VOCAB * 8)

// precompute smem: ws[i][k*32+eL] padded row stride 164 floats
#define WROW 164
#define PRE_SMEM (D_EMB * WROW * 4)   // 83,968 B
#define PRE_THREADS 160

// fp16 contrib table: [tap][vocab][emb]
__device__ __align__(16) __half g_tab[NTAP * D_VOCAB * D_EMB];

// ---------------------------------------------------------------------------
// Fused transpose+precompute:
//   contrib[k][v][e] = sum_i conv_w[e,i,k] * emb[v,i]  (fp32 -> fp16)
// Grid (33, 4): x = 8-vocab group, y = 32-e group. 160 threads.
// Phase 1: stage conv_w rows e0..e0+31 (80 KB) coalesced, transposed into
//          smem ws[i][k*32+eL] (padded stride). Phase 2: thread (k,eL) FMAs
//          over i with broadcast emb float4 reads.
// ---------------------------------------------------------------------------
__global__ void __launch_bounds__(PRE_THREADS, 1)
precompute_fused(const float* __restrict__ conv_w,
                 const float* __restrict__ emb) {
    extern __shared__ float ws[];
    const int tid = threadIdx.x;
    const int v0 = blockIdx.x * 8;
    const int e0 = blockIdx.y * 32;

    // Stage: 32 e-rows x 640 floats. Per r: 160 threads x float4 = whole row.
    const float4* __restrict__ cw4 = (const float4*)conv_w;
    #pragma unroll 4
    for (int r = 0; r < 32; ++r) {
        float4 w = __ldg(&cw4[(size_t)(e0 + r) * 160 + tid]);
        const int j = 4 * tid;
        ws[((j + 0) / 5) * WROW + ((j + 0) % 5) * 32 + r] = w.x;
        ws[((j + 1) / 5) * WROW + ((j + 1) % 5) * 32 + r] = w.y;
        ws[((j + 2) / 5) * WROW + ((j + 2) % 5) * 32 + r] = w.z;
        ws[((j + 3) / 5) * WROW + ((j + 3) % 5) * 32 + r] = w.w;
    }
    __syncthreads();

    const int k = tid >> 5;          // 0..4
    const int eL = tid & 31;
    const float* __restrict__ wcol = ws + k * 32 + eL;
    const float4* __restrict__ emb4 = (const float4*)emb;

    float acc[8];
    #pragma unroll
    for (int v = 0; v < 8; ++v) acc[v] = 0.f;

    #pragma unroll 4
    for (int i4 = 0; i4 < 32; ++i4) {
        const float w0 = wcol[(i4 * 4 + 0) * WROW];
        const float w1 = wcol[(i4 * 4 + 1) * WROW];
        const float w2 = wcol[(i4 * 4 + 2) * WROW];
        const float w3 = wcol[(i4 * 4 + 3) * WROW];
        #pragma unroll
        for (int v = 0; v < 8; ++v) {
            const int vv = v0 + v;
            if (vv < D_VOCAB) {
                float4 em = __ldg(&emb4[vv * 32 + i4]);
                acc[v] = fmaf(em.x, w0, acc[v]);
                acc[v] = fmaf(em.y, w1, acc[v]);
                acc[v] = fmaf(em.z, w2, acc[v]);
                acc[v] = fmaf(em.w, w3, acc[v]);
            }
        }
    }

    #pragma unroll
    for (int v = 0; v < 8; ++v) {
        const int vv = v0 + v;
        if (vv < D_VOCAB)
            g_tab[(k * D_VOCAB + vv) * D_EMB + e0 + eL] = __float2half(acc[v]);
    }
}

// ---------------------------------------------------------------------------
// half2 x4 helpers on uint4-packed fp16
// ---------------------------------------------------------------------------
__device__ __forceinline__ uint4 h2add4(uint4 a, uint4 b) {
    uint4 r;
    *(__half2*)&r.x = __hadd2(*(const __half2*)&a.x, *(const __half2*)&b.x);
    *(__half2*)&r.y = __hadd2(*(const __half2*)&a.y, *(const __half2*)&b.y);
    *(__half2*)&r.z = __hadd2(*(const __half2*)&a.z, *(const __half2*)&b.z);
    *(__half2*)&r.w = __hadd2(*(const __half2*)&a.w, *(const __half2*)&b.w);
    return r;
}
__device__ __forceinline__ uint4 h2max4(uint4 a, uint4 b) {
    uint4 r;
    *(__half2*)&r.x = __hmax2(*(const __half2*)&a.x, *(const __half2*)&b.x);
    *(__half2*)&r.y = __hmax2(*(const __half2*)&a.y, *(const __half2*)&b.y);
    *(__half2*)&r.z = __hmax2(*(const __half2*)&a.z, *(const __half2*)&b.z);
    *(__half2*)&r.w = __hmax2(*(const __half2*)&a.w, *(const __half2*)&b.w);
    return r;
}

// ---------------------------------------------------------------------------
// Main kernel. Grid (74, 2): x = sequence chunk (443 seqs), y = 64-ch group.
// CTA stages its 5x262x64 fp16 table slice (164 KB smem), 1 CTA/SM, 1 wave.
// Quarter-warp split: lane group q = lane>>3 -> sequence n0+q; lane owns
// 8 channels (16 B) -> LDS.128 gathers, conflict-free, 4 chains per warp.
// Id loads software-pipelined: first batch issued before table staging,
// next batch issued before each t-loop.
// ---------------------------------------------------------------------------
__global__ void __launch_bounds__(THREADS, 1)
conv_char_kernel(const int* __restrict__ ids_raw,
                 const float* __restrict__ conv_b,
                 float* __restrict__ out) {
    extern __shared__ uint4 s_tab16[];
    const int g = blockIdx.y;
    const int lane = threadIdx.x & 31;
    const int warp = threadIdx.x >> 5;
    const int l7 = lane & 7;
    const int q = lane >> 3;             // 0..3: which sequence of the group

    // Per-warp int64-vs-int32 detection (no shared, no sync needed).
    int s2;
    {
        int v = ids_raw[2 * lane + 1] | ids_raw[64 + 2 * lane + 1];
        s2 = (__ballot_sync(0xffffffffu, v != 0) == 0u) ? 1 : 0;
    }

    const int chunk = (NSEQ + NCHUNK - 1) / NCHUNK;  // 443
    const int base = blockIdx.x * chunk;
    const int end = min(base + chunk, NSEQ);
    const int step = 4 * (THREADS / 32);

    // Prefetch first iteration's raw id words BEFORE staging (overlaps).
    uint4 raw[8];
    {
        const int nc = min(base + 4 * warp + q, end - 1);
        if (s2) {
            const uint4* p = (const uint4*)(ids_raw + (size_t)nc * 32);
            #pragma unroll
            for (int j = 0; j < 8; ++j) raw[j] = __ldg(&p[j]);
        } else {
            const uint4* p = (const uint4*)(ids_raw + (size_t)nc * 16);
            #pragma unroll
            for (int j = 0; j < 4; ++j) raw[j] = __ldg(&p[j]);
        }
    }

    // Stage table slice: coalesced uint4 copies (10480 x 16 B).
    {
        const char* gb = (const char*)g_tab;
        for (int idx = threadIdx.x; idx < NTAP * D_VOCAB * 8; idx += THREADS) {
            int r = idx >> 3, c = idx & 7;
            s_tab16[idx] = *(const uint4*)(gb + (size_t)r * 256 + g * 128 + c * 16);
        }
    }
    __syncthreads();

    const float4 bias0 = *(const float4*)(conv_b + g * 64 + l7 * 8);
    const float4 bias1 = *(const float4*)(conv_b + g * 64 + l7 * 8 + 4);

    for (int n0 = base + 4 * warp; n0 < end; n0 += step) {
        const int nsel = n0 + q;

        // Convert raw -> gather indices a[c] = id*8 + l7.
        int a[CW];
        if (s2) {
            #pragma unroll
            for (int j = 0; j < 8; ++j) {
                a[2 * j]     = (int)raw[j].x * 8 + l7;
                a[2 * j + 1] = (int)raw[j].z * 8 + l7;
            }
        } else {
            #pragma unroll
            for (int j = 0; j < 4; ++j) {
                a[4 * j]     = (int)raw[j].x * 8 + l7;
                a[4 * j + 1] = (int)raw[j].y * 8 + l7;
                a[4 * j + 2] = (int)raw[j].z * 8 + l7;
                a[4 * j + 3] = (int)raw[j].w * 8 + l7;
            }
        }

        // Issue next iteration's id loads now; latency hides under t-loop.
        {
            const int nn = n0 + step + q;
            const int nc = min(nn < end ? nn : (end - 1), end - 1);
            if (s2) {
                const uint4* p = (const uint4*)(ids_raw + (size_t)nc * 32);
                #pragma unroll
                for (int j = 0; j < 8; ++j) raw[j] = __ldg(&p[j]);
            } else {
                const uint4* p = (const uint4*)(ids_raw + (size_t)nc * 16);
                #pragma unroll
                for (int j = 0; j < 4; ++j) raw[j] = __ldg(&p[j]);
            }
        }

        // Even/odd-t max chains on 8 channels (4 half2) per lane.
        uint4 me, mo;
        #pragma unroll
        for (int t = 0; t < CW; ++t) {
            const int klo = (t < 2) ? (2 - t) : 0;
            const int khi = (t > CW - 3) ? (CW + 1 - t) : NTAP - 1;  // inclusive

            uint4 s[NTAP];
            #pragma unroll
            for (int k = 0; k < NTAP; ++k) {
                if (k < klo || k > khi) continue;
                s[k] = s_tab16[k * TAPSTRIDE16 + a[t + k - 2]];
            }

            uint4 y;
            const int nv = khi - klo + 1;
            if (nv == 5) {
                y = h2add4(h2add4(h2add4(s[0], s[1]), h2add4(s[2], s[3])), s[4]);
            } else if (nv == 4) {
                y = h2add4(h2add4(s[klo], s[klo + 1]), h2add4(s[klo + 2], s[klo + 3]));
            } else {  // nv == 3
                y = h2add4(h2add4(s[klo], s[klo + 1]), s[klo + 2]);
            }

            if (t == 0)      me = y;
            else if (t == 1) mo = y;
            else if ((t & 1) == 0) me = h2max4(me, y);
            else                   mo = h2max4(mo, y);
        }
        const uint4 m = h2max4(me, mo);

        if (nsel < end) {
            float2 c0 = __half22float2(*(const __half2*)&m.x);
            float2 c1 = __half22float2(*(const __half2*)&m.y);
            float2 c2 = __half22float2(*(const __half2*)&m.z);
            float2 c3 = __half22float2(*(const __half2*)&m.w);
            float4 o0, o1;
            o0.x = c0.x + bias0.x; o0.y = c0.y + bias0.y;
            o0.z = c1.x + bias0.z; o0.w = c1.y + bias0.w;
            o1.x = c2.x + bias1.x; o1.y = c2.y + bias1.y;
            o1.z = c3.x + bias1.z; o1.w = c3.y + bias1.w;
            float* op = out + (size_t)nsel * D_EMB + g * 64 + l7 * 8;
            *(float4*)op = o0;
            *(float4*)(op + 4) = o1;
        }
    }
}

// ---------------------------------------------------------------------------
extern "C" void kernel_launch(void* const* d_in, const int* in_sizes, int n_in,
                              void* d_out, int out_size) {
    const int* input = nullptr;
    const float* emb = nullptr;
    const float* conv_w = nullptr;
    const float* conv_b = nullptr;
    for (int i = 0; i < n_in; ++i) {
        switch (in_sizes[i]) {
            case 524288: input  = (const int*)d_in[i];   break;  // ids [128,256,16]
            case 33536:  emb    = (const float*)d_in[i]; break;  // [262,128]
            case 81920:  conv_w = (const float*)d_in[i]; break;  // [128,128,5]
            case 128:    conv_b = (const float*)d_in[i]; break;  // [128]
            default: break;  // lengths (32768) unused
        }
    }

    cudaFuncSetAttribute(precompute_fused,
                         cudaFuncAttributeMaxDynamicSharedMemorySize, PRE_SMEM);
    precompute_fused<<<dim3(33, 4), PRE_THREADS, PRE_SMEM>>>(conv_w, emb);

    cudaFuncSetAttribute(conv_char_kernel,
                         cudaFuncAttributeMaxDynamicSharedMemorySize, SMEM_BYTES);
    conv_char_kernel<<<dim3(NCHUNK, 2), THREADS, SMEM_BYTES>>>(
        input, conv_b, (float*)d_out);
}